// round 1
// baseline (speedup 1.0000x reference)
#include <cuda_runtime.h>

#define BATCH 2
#define NN    4096
#define CINN  128
#define CC    64
#define TOTROWS (BATCH * NN)   // 8192
#define HOUT_ELEMS (TOTROWS * CC)  // 524288

// ---------------- scratch (device globals; no allocation allowed) ----------
__device__ float g_h[TOTROWS * CC];   // 2 MB
__device__ float g_u[TOTROWS];
__device__ float g_v[TOTROWS];
__device__ float g_invS[TOTROWS];

__device__ __forceinline__ float sigmoidf(float x) {
    return 1.0f / (1.0f + __expf(-x));
}

// ===========================================================================
// Kernel 1: h = relu(relu(x@W1+b1)@W2+b2); u = h@Wa[:C]; v = h@Wa[C:]
// 32 rows per block, 256 threads (4 row-groups x 64 channels), weights in smem
// ===========================================================================
extern __shared__ float s1[];

__global__ void k1_mlp(const float* __restrict__ x,
                       const float* __restrict__ W1,
                       const float* __restrict__ b1,
                       const float* __restrict__ W2,
                       const float* __restrict__ b2,
                       const float* __restrict__ Wa)
{
    float* sW1 = s1;             // 8192 floats  [i][ch]
    float* sW2 = sW1 + 8192;     // 4096 floats  [i][ch]
    float* sWa = sW2 + 4096;     // 128 floats
    float* sX  = sWa + 128;      // 4096 floats  [r][i]  (reused as sH2 later)
    float* sH1 = sX + 4096;      // 2048 floats  [r][ch]

    const int t = threadIdx.x;
    const int grow0 = blockIdx.x * 32;

    // cooperative float4 loads
    {
        const float4* W1v = (const float4*)W1;
        float4* d = (float4*)sW1;
        #pragma unroll
        for (int p = t; p < 2048; p += 256) d[p] = W1v[p];
        const float4* W2v = (const float4*)W2;
        float4* d2 = (float4*)sW2;
        #pragma unroll
        for (int p = t; p < 1024; p += 256) d2[p] = W2v[p];
        if (t < 32) ((float4*)sWa)[t] = ((const float4*)Wa)[t];
        const float4* Xv = (const float4*)(x + (long)grow0 * CINN);
        float4* dx = (float4*)sX;
        #pragma unroll
        for (int p = t; p < 1024; p += 256) dx[p] = Xv[p];
    }
    __syncthreads();

    const int ch = t & 63;
    const int rg = t >> 6;     // 0..3
    const float bb1 = b1[ch];
    const float bb2 = b2[ch];

    // ---- layer 1: h1 = relu(x@W1 + b1) ----
    float acc[8];
    #pragma unroll
    for (int k = 0; k < 8; k++) acc[k] = bb1;

    #pragma unroll 4
    for (int i = 0; i < CINN; i += 4) {
        float w0 = sW1[(i + 0) * 64 + ch];
        float w1 = sW1[(i + 1) * 64 + ch];
        float w2 = sW1[(i + 2) * 64 + ch];
        float w3 = sW1[(i + 3) * 64 + ch];
        #pragma unroll
        for (int k = 0; k < 8; k++) {
            const float4 x4 = *(const float4*)(sX + (rg + 4 * k) * CINN + i);
            acc[k] = fmaf(x4.x, w0, acc[k]);
            acc[k] = fmaf(x4.y, w1, acc[k]);
            acc[k] = fmaf(x4.z, w2, acc[k]);
            acc[k] = fmaf(x4.w, w3, acc[k]);
        }
    }
    #pragma unroll
    for (int k = 0; k < 8; k++)
        sH1[(rg + 4 * k) * 64 + ch] = fmaxf(acc[k], 0.0f);
    __syncthreads();   // sX reads done; sH1 complete

    // ---- layer 2: h2 = relu(h1@W2 + b2) ----
    #pragma unroll
    for (int k = 0; k < 8; k++) acc[k] = bb2;

    #pragma unroll 4
    for (int i = 0; i < CC; i += 4) {
        float w0 = sW2[(i + 0) * 64 + ch];
        float w1 = sW2[(i + 1) * 64 + ch];
        float w2 = sW2[(i + 2) * 64 + ch];
        float w3 = sW2[(i + 3) * 64 + ch];
        #pragma unroll
        for (int k = 0; k < 8; k++) {
            const float4 h4 = *(const float4*)(sH1 + (rg + 4 * k) * 64 + i);
            acc[k] = fmaf(h4.x, w0, acc[k]);
            acc[k] = fmaf(h4.y, w1, acc[k]);
            acc[k] = fmaf(h4.z, w2, acc[k]);
            acc[k] = fmaf(h4.w, w3, acc[k]);
        }
    }

    float* sH2 = sX;   // reuse (sX no longer read after the sync above)
    #pragma unroll
    for (int k = 0; k < 8; k++) {
        const int r = rg + 4 * k;
        const float h2 = fmaxf(acc[k], 0.0f);
        g_h[(long)(grow0 + r) * CC + ch] = h2;
        sH2[r * 64 + ch] = h2;
    }
    __syncthreads();

    // ---- u, v reduction: warp w handles rows 4w..4w+3 ----
    const int w = t >> 5, lane = t & 31;
    for (int rr = w * 4; rr < w * 4 + 4; rr++) {
        const float a0 = sH2[rr * 64 + lane];
        const float a1 = sH2[rr * 64 + lane + 32];
        float up = a0 * sWa[lane]      + a1 * sWa[lane + 32];
        float vp = a0 * sWa[64 + lane] + a1 * sWa[96 + lane];
        #pragma unroll
        for (int off = 16; off > 0; off >>= 1) {
            up += __shfl_down_sync(0xffffffffu, up, off);
            vp += __shfl_down_sync(0xffffffffu, vp, off);
        }
        if (lane == 0) { g_u[grow0 + rr] = up; g_v[grow0 + rr] = vp; }
    }
}

// ===========================================================================
// Kernel 2: row sums.  4 rows per block, 256 threads (64 per row).
// ===========================================================================
__global__ void k2_rowsum(const float* __restrict__ adj,
                          const float* __restrict__ ba)
{
    __shared__ __align__(16) float sV[NN];
    __shared__ float sRed[8];

    const int t = threadIdx.x;
    const int grow0 = blockIdx.x * 4;
    const int b = grow0 >> 12;

    {
        const float4* vv = (const float4*)(g_v + (long)b * NN);
        float4* d = (float4*)sV;
        #pragma unroll
        for (int p = t; p < 1024; p += 256) d[p] = vv[p];
    }
    __syncthreads();

    const int rg = t >> 6, l64 = t & 63;
    const int grow = grow0 + rg;
    const float u = g_u[grow] + ba[0];
    const float4* ar = (const float4*)(adj + (long)grow * NN);

    float s = 0.0f;
    #pragma unroll 4
    for (int it = 0; it < 16; it++) {
        const int f = l64 + 64 * it;
        const float4 a4 = ar[f];
        const int j = f * 4;
        s += a4.x * sigmoidf(u + sV[j + 0]);
        s += a4.y * sigmoidf(u + sV[j + 1]);
        s += a4.z * sigmoidf(u + sV[j + 2]);
        s += a4.w * sigmoidf(u + sV[j + 3]);
    }
    #pragma unroll
    for (int off = 16; off > 0; off >>= 1)
        s += __shfl_down_sync(0xffffffffu, s, off);
    const int w = t >> 5, lane = t & 31;
    if (lane == 0) sRed[w] = s;
    __syncthreads();
    if (t < 4) {
        const float S = sRed[2 * t] + sRed[2 * t + 1];
        g_invS[grow0 + t] = 1.0f / (S + 1e-10f);
    }
}

// ===========================================================================
// Kernel 3 (fused): per 32-row tile, stream j in 64-wide chunks.
// Recompute e, normalize, write a, and accumulate h_out = a @ h via a
// register-blocked (2 rows x 4 ch) smem GEMM.
// ===========================================================================
#define TI 32
#define JC 64
#define SE_STRIDE 33   // sE[jj][r], padded to break bank conflicts on store

__global__ void k3_fused(const float* __restrict__ adj,
                         const float* __restrict__ ba,
                         float* __restrict__ out_h,
                         float* __restrict__ out_a)
{
    __shared__ __align__(16) float sE[JC * SE_STRIDE];  // normalized a tile [jj][r]
    __shared__ __align__(16) float sH[JC * CC];         // h tile [jj][c]
    __shared__ __align__(16) float sV[NN];
    __shared__ float sU[TI];
    __shared__ float sInv[TI];

    const int t = threadIdx.x;
    const int grow0 = blockIdx.x * TI;
    const int b = grow0 >> 12;

    {
        const float4* vv = (const float4*)(g_v + (long)b * NN);
        float4* d = (float4*)sV;
        #pragma unroll
        for (int p = t; p < 1024; p += 256) d[p] = vv[p];
        if (t < TI) { sU[t] = g_u[grow0 + t]; sInv[t] = g_invS[grow0 + t]; }
    }
    const float bav = ba[0];

    const int tr = t >> 4;   // 0..15  -> rows 2*tr, 2*tr+1
    const int tc = t & 15;   // 0..15  -> cols 4*tc..4*tc+3

    float acc[2][4];
    #pragma unroll
    for (int i = 0; i < 2; i++)
        #pragma unroll
        for (int q = 0; q < 4; q++) acc[i][q] = 0.0f;

    const float* hbase = g_h + (long)b * NN * CC;

    for (int j0 = 0; j0 < NN; j0 += JC) {
        __syncthreads();   // previous GEMM done (also covers the sV/sU loads)

        // load h tile [JC][CC]
        {
            const float4* hv = (const float4*)(hbase + (long)j0 * CC);
            float4* d = (float4*)sH;
            #pragma unroll
            for (int p = t; p < (JC * CC / 4); p += 256) d[p] = hv[p];
        }

        // compute normalized attention tile, write 'a' to gmem, stage in sE
        #pragma unroll
        for (int k = 0; k < 2; k++) {
            const int p = t + 256 * k;
            const int r = p >> 4;        // 0..31
            const int jc4 = p & 15;      // float4 column index
            const int grow = grow0 + r;
            const float4 a4 = ((const float4*)(adj + (long)grow * NN + j0))[jc4];
            const float u = sU[r] + bav;
            const float inv = sInv[r];
            const int jj = jc4 * 4;
            const float e0 = a4.x * sigmoidf(u + sV[j0 + jj + 0]) * inv;
            const float e1 = a4.y * sigmoidf(u + sV[j0 + jj + 1]) * inv;
            const float e2 = a4.z * sigmoidf(u + sV[j0 + jj + 2]) * inv;
            const float e3 = a4.w * sigmoidf(u + sV[j0 + jj + 3]) * inv;
            float4 o; o.x = e0; o.y = e1; o.z = e2; o.w = e3;
            ((float4*)(out_a + (long)grow * NN + j0))[jc4] = o;
            sE[(jj + 0) * SE_STRIDE + r] = e0;
            sE[(jj + 1) * SE_STRIDE + r] = e1;
            sE[(jj + 2) * SE_STRIDE + r] = e2;
            sE[(jj + 3) * SE_STRIDE + r] = e3;
        }
        __syncthreads();

        // GEMM: acc += sE^T(chunk) @ sH(chunk)
        #pragma unroll 16
        for (int jj = 0; jj < JC; jj++) {
            const float e0 = sE[jj * SE_STRIDE + 2 * tr + 0];
            const float e1 = sE[jj * SE_STRIDE + 2 * tr + 1];
            const float4 h4 = *(const float4*)(sH + jj * CC + 4 * tc);
            acc[0][0] = fmaf(e0, h4.x, acc[0][0]);
            acc[0][1] = fmaf(e0, h4.y, acc[0][1]);
            acc[0][2] = fmaf(e0, h4.z, acc[0][2]);
            acc[0][3] = fmaf(e0, h4.w, acc[0][3]);
            acc[1][0] = fmaf(e1, h4.x, acc[1][0]);
            acc[1][1] = fmaf(e1, h4.y, acc[1][1]);
            acc[1][2] = fmaf(e1, h4.z, acc[1][2]);
            acc[1][3] = fmaf(e1, h4.w, acc[1][3]);
        }
    }

    // write h_out
    #pragma unroll
    for (int i = 0; i < 2; i++) {
        float4 o;
        o.x = acc[i][0]; o.y = acc[i][1]; o.z = acc[i][2]; o.w = acc[i][3];
        *(float4*)(out_h + (long)(grow0 + 2 * tr + i) * CC + 4 * tc) = o;
    }
}

// ===========================================================================
extern "C" void kernel_launch(void* const* d_in, const int* in_sizes, int n_in,
                              void* d_out, int out_size)
{
    const float* x   = (const float*)d_in[0];
    const float* adj = (const float*)d_in[1];
    const float* W1  = (const float*)d_in[2];
    const float* b1  = (const float*)d_in[3];
    const float* W2  = (const float*)d_in[4];
    const float* b2  = (const float*)d_in[5];
    const float* Wa  = (const float*)d_in[6];
    const float* ba  = (const float*)d_in[7];

    float* out_h = (float*)d_out;
    float* out_a = (float*)d_out + HOUT_ELEMS;

    const int k1_smem = (8192 + 4096 + 128 + 4096 + 2048) * 4;  // 74240 B
    cudaFuncSetAttribute(k1_mlp, cudaFuncAttributeMaxDynamicSharedMemorySize, k1_smem);

    k1_mlp<<<TOTROWS / 32, 256, k1_smem>>>(x, W1, b1, W2, b2, Wa);
    k2_rowsum<<<TOTROWS / 4, 256>>>(adj, ba);
    k3_fused<<<TOTROWS / TI, 256>>>(adj, ba, out_h, out_a);
}

// round 2
// speedup vs baseline: 1.2536x; 1.2536x over previous
#include <cuda_runtime.h>

#define BATCH 2
#define NN    4096
#define CINN  128
#define CC    64
#define TOTROWS (BATCH * NN)       // 8192
#define HOUT_ELEMS (TOTROWS * CC)  // 524288

// ---------------- scratch (device globals; no allocation allowed) ----------
__device__ float g_h[TOTROWS * CC];   // 2 MB
__device__ float g_u[TOTROWS];
__device__ float g_v[TOTROWS];
__device__ float g_invS[TOTROWS];

__device__ __forceinline__ float sigmoidf(float x) {
    return __fdividef(1.0f, 1.0f + __expf(-x));
}

// packed f32x2 helpers -------------------------------------------------------
__device__ __forceinline__ unsigned long long bcast2(float x) {
    unsigned long long r;
    unsigned u = __float_as_uint(x);
    asm("mov.b64 %0, {%1, %2};" : "=l"(r) : "r"(u), "r"(u));
    return r;
}
#define FMA2(d, a, b) asm("fma.rn.f32x2 %0, %1, %2, %0;" : "+l"(d) : "l"(a), "l"(b))
__device__ __forceinline__ float2 unpack2(unsigned long long v) {
    unsigned lo, hi;
    asm("mov.b64 {%0, %1}, %2;" : "=r"(lo), "=r"(hi) : "l"(v));
    float2 f; f.x = __uint_as_float(lo); f.y = __uint_as_float(hi);
    return f;
}

// ===========================================================================
// Kernel 1: h = relu(relu(x@W1+b1)@W2+b2); u = h@Wa[:C]; v = h@Wa[C:]
// ===========================================================================
extern __shared__ float s1[];

__global__ void k1_mlp(const float* __restrict__ x,
                       const float* __restrict__ W1,
                       const float* __restrict__ b1,
                       const float* __restrict__ W2,
                       const float* __restrict__ b2,
                       const float* __restrict__ Wa)
{
    float* sW1 = s1;             // 8192 floats  [i][ch]
    float* sW2 = sW1 + 8192;     // 4096 floats  [i][ch]
    float* sWa = sW2 + 4096;     // 128 floats
    float* sX  = sWa + 128;      // 4096 floats  [r][i]  (reused as sH2 later)
    float* sH1 = sX + 4096;      // 2048 floats  [r][ch]

    const int t = threadIdx.x;
    const int grow0 = blockIdx.x * 32;

    {
        const float4* W1v = (const float4*)W1;
        float4* d = (float4*)sW1;
        #pragma unroll
        for (int p = t; p < 2048; p += 256) d[p] = W1v[p];
        const float4* W2v = (const float4*)W2;
        float4* d2 = (float4*)sW2;
        #pragma unroll
        for (int p = t; p < 1024; p += 256) d2[p] = W2v[p];
        if (t < 32) ((float4*)sWa)[t] = ((const float4*)Wa)[t];
        const float4* Xv = (const float4*)(x + (long)grow0 * CINN);
        float4* dx = (float4*)sX;
        #pragma unroll
        for (int p = t; p < 1024; p += 256) dx[p] = Xv[p];
    }
    __syncthreads();

    const int ch = t & 63;
    const int rg = t >> 6;     // 0..3
    const float bb1 = b1[ch];
    const float bb2 = b2[ch];

    float acc[8];
    #pragma unroll
    for (int k = 0; k < 8; k++) acc[k] = bb1;

    #pragma unroll 4
    for (int i = 0; i < CINN; i += 4) {
        float w0 = sW1[(i + 0) * 64 + ch];
        float w1 = sW1[(i + 1) * 64 + ch];
        float w2 = sW1[(i + 2) * 64 + ch];
        float w3 = sW1[(i + 3) * 64 + ch];
        #pragma unroll
        for (int k = 0; k < 8; k++) {
            const float4 x4 = *(const float4*)(sX + (rg + 4 * k) * CINN + i);
            acc[k] = fmaf(x4.x, w0, acc[k]);
            acc[k] = fmaf(x4.y, w1, acc[k]);
            acc[k] = fmaf(x4.z, w2, acc[k]);
            acc[k] = fmaf(x4.w, w3, acc[k]);
        }
    }
    #pragma unroll
    for (int k = 0; k < 8; k++)
        sH1[(rg + 4 * k) * 64 + ch] = fmaxf(acc[k], 0.0f);
    __syncthreads();

    #pragma unroll
    for (int k = 0; k < 8; k++) acc[k] = bb2;

    #pragma unroll 4
    for (int i = 0; i < CC; i += 4) {
        float w0 = sW2[(i + 0) * 64 + ch];
        float w1 = sW2[(i + 1) * 64 + ch];
        float w2 = sW2[(i + 2) * 64 + ch];
        float w3 = sW2[(i + 3) * 64 + ch];
        #pragma unroll
        for (int k = 0; k < 8; k++) {
            const float4 h4 = *(const float4*)(sH1 + (rg + 4 * k) * 64 + i);
            acc[k] = fmaf(h4.x, w0, acc[k]);
            acc[k] = fmaf(h4.y, w1, acc[k]);
            acc[k] = fmaf(h4.z, w2, acc[k]);
            acc[k] = fmaf(h4.w, w3, acc[k]);
        }
    }

    float* sH2 = sX;
    #pragma unroll
    for (int k = 0; k < 8; k++) {
        const int r = rg + 4 * k;
        const float h2 = fmaxf(acc[k], 0.0f);
        g_h[(long)(grow0 + r) * CC + ch] = h2;
        sH2[r * 64 + ch] = h2;
    }
    __syncthreads();

    const int w = t >> 5, lane = t & 31;
    for (int rr = w * 4; rr < w * 4 + 4; rr++) {
        const float a0 = sH2[rr * 64 + lane];
        const float a1 = sH2[rr * 64 + lane + 32];
        float up = a0 * sWa[lane]      + a1 * sWa[lane + 32];
        float vp = a0 * sWa[64 + lane] + a1 * sWa[96 + lane];
        #pragma unroll
        for (int off = 16; off > 0; off >>= 1) {
            up += __shfl_down_sync(0xffffffffu, up, off);
            vp += __shfl_down_sync(0xffffffffu, vp, off);
        }
        if (lane == 0) { g_u[grow0 + rr] = up; g_v[grow0 + rr] = vp; }
    }
}

// ===========================================================================
// Kernel 2: row sums.
// ===========================================================================
__global__ void k2_rowsum(const float* __restrict__ adj,
                          const float* __restrict__ ba)
{
    __shared__ __align__(16) float sV[NN];
    __shared__ float sRed[8];

    const int t = threadIdx.x;
    const int grow0 = blockIdx.x * 4;
    const int b = grow0 >> 12;

    {
        const float4* vv = (const float4*)(g_v + (long)b * NN);
        float4* d = (float4*)sV;
        #pragma unroll
        for (int p = t; p < 1024; p += 256) d[p] = vv[p];
    }
    __syncthreads();

    const int rg = t >> 6, l64 = t & 63;
    const int grow = grow0 + rg;
    const float u = g_u[grow] + ba[0];
    const float4* ar = (const float4*)(adj + (long)grow * NN);

    float s = 0.0f;
    #pragma unroll 4
    for (int it = 0; it < 16; it++) {
        const int f = l64 + 64 * it;
        const float4 a4 = __ldcs(ar + f);
        const int j = f * 4;
        s += a4.x * sigmoidf(u + sV[j + 0]);
        s += a4.y * sigmoidf(u + sV[j + 1]);
        s += a4.z * sigmoidf(u + sV[j + 2]);
        s += a4.w * sigmoidf(u + sV[j + 3]);
    }
    #pragma unroll
    for (int off = 16; off > 0; off >>= 1)
        s += __shfl_down_sync(0xffffffffu, s, off);
    const int w = t >> 5, lane = t & 31;
    if (lane == 0) sRed[w] = s;
    __syncthreads();
    if (t < 4) {
        const float S = sRed[2 * t] + sRed[2 * t + 1];
        g_invS[grow0 + t] = 1.0f / (S + 1e-10f);
    }
}

// ===========================================================================
// Kernel 3 (fused, pipelined, f32x2 GEMM)
// ===========================================================================
#define TI 32
#define JC 64

__global__ void __launch_bounds__(256, 2)
k3_fused(const float* __restrict__ adj,
         const float* __restrict__ ba,
         float* __restrict__ out_h,
         float* __restrict__ out_a)
{
    __shared__ __align__(16) float sE[TI * JC];   // normalized a tile [r][jj]  8KB
    __shared__ __align__(16) float sH[JC * CC];   // h tile [jj][c]            16KB
    __shared__ __align__(16) float sV[NN];        //                           16KB
    __shared__ float sU[TI];
    __shared__ float sInv[TI];

    const int t = threadIdx.x;
    const int grow0 = blockIdx.x * TI;
    const int b = grow0 >> 12;

    {
        const float4* vv = (const float4*)(g_v + (long)b * NN);
        float4* d = (float4*)sV;
        #pragma unroll
        for (int p = t; p < 1024; p += 256) d[p] = vv[p];
        if (t < TI) { sU[t] = g_u[grow0 + t]; sInv[t] = g_invS[grow0 + t]; }
    }
    const float bav = ba[0];

    const int tr = t >> 4;   // 0..15  -> rows 2*tr, 2*tr+1
    const int tc = t & 15;   // 0..15  -> cols 4*tc..4*tc+3

    unsigned long long acc00 = 0, acc01 = 0, acc10 = 0, acc11 = 0;

    const float* hbase = g_h + (long)b * NN * CC;

    // e-pass index decomposition (2 float4 per thread per chunk)
    const int er0  = t >> 4;          // row for k=0 slice (0..15)
    const int er1  = (t + 256) >> 4;  // row for k=1 slice (16..31)
    const int ejc  = t & 15;          // float4 column index

    float4 pa0, pa1;     // prefetched adj
    float4 ph0, ph1, ph2, ph3;  // prefetched h tile

    // prologue: prefetch chunk 0
    pa0 = __ldcs((const float4*)(adj + (long)(grow0 + er0) * NN) + ejc);
    pa1 = __ldcs((const float4*)(adj + (long)(grow0 + er1) * NN) + ejc);
    {
        const float4* hv = (const float4*)hbase;
        ph0 = hv[t];
        ph1 = hv[t + 256];
        ph2 = hv[t + 512];
        ph3 = hv[t + 768];
    }

    for (int c = 0; c < NN / JC; c++) {
        const int j0 = c * JC;
        __syncthreads();   // previous GEMM done; sV/sU ready on c=0

        // store h tile
        {
            float4* d = (float4*)sH;
            d[t]       = ph0;
            d[t + 256] = ph1;
            d[t + 512] = ph2;
            d[t + 768] = ph3;
        }
        // compute normalized attention tile -> out_a + sE
        #pragma unroll
        for (int k = 0; k < 2; k++) {
            const int r  = k ? er1 : er0;
            const float4 a4 = k ? pa1 : pa0;
            const int grow = grow0 + r;
            const float u = sU[r] + bav;
            const float inv = sInv[r];
            const int jj = ejc * 4;
            float4 o;
            o.x = a4.x * sigmoidf(u + sV[j0 + jj + 0]) * inv;
            o.y = a4.y * sigmoidf(u + sV[j0 + jj + 1]) * inv;
            o.z = a4.z * sigmoidf(u + sV[j0 + jj + 2]) * inv;
            o.w = a4.w * sigmoidf(u + sV[j0 + jj + 3]) * inv;
            __stcs((float4*)(out_a + (long)grow * NN + j0) + ejc, o);
            *(float4*)(sE + r * JC + jj) = o;
        }
        __syncthreads();

        // prefetch next chunk (LDG latency hides under the GEMM)
        if (c + 1 < NN / JC) {
            const int jn = j0 + JC;
            pa0 = __ldcs((const float4*)(adj + (long)(grow0 + er0) * NN + jn) + ejc);
            pa1 = __ldcs((const float4*)(adj + (long)(grow0 + er1) * NN + jn) + ejc);
            const float4* hv = (const float4*)(hbase + (long)jn * CC);
            ph0 = hv[t];
            ph1 = hv[t + 256];
            ph2 = hv[t + 512];
            ph3 = hv[t + 768];
        }

        // GEMM: acc += sE(rows)^ * sH(chunk), packed f32x2
        #pragma unroll 16
        for (int jj = 0; jj < JC; jj++) {
            const float e0 = sE[(2 * tr) * JC + jj];
            const float e1 = sE[(2 * tr + 1) * JC + jj];
            const unsigned long long ee0 = bcast2(e0);
            const unsigned long long ee1 = bcast2(e1);
            const ulonglong2 hp = *(const ulonglong2*)(sH + jj * CC + 4 * tc);
            FMA2(acc00, ee0, hp.x);
            FMA2(acc01, ee0, hp.y);
            FMA2(acc10, ee1, hp.x);
            FMA2(acc11, ee1, hp.y);
        }
    }

    // write h_out
    {
        const float2 a = unpack2(acc00), bq = unpack2(acc01);
        float4 o; o.x = a.x; o.y = a.y; o.z = bq.x; o.w = bq.y;
        *(float4*)(out_h + (long)(grow0 + 2 * tr) * CC + 4 * tc) = o;
    }
    {
        const float2 a = unpack2(acc10), bq = unpack2(acc11);
        float4 o; o.x = a.x; o.y = a.y; o.z = bq.x; o.w = bq.y;
        *(float4*)(out_h + (long)(grow0 + 2 * tr + 1) * CC + 4 * tc) = o;
    }
}

// ===========================================================================
extern "C" void kernel_launch(void* const* d_in, const int* in_sizes, int n_in,
                              void* d_out, int out_size)
{
    const float* x   = (const float*)d_in[0];
    const float* adj = (const float*)d_in[1];
    const float* W1  = (const float*)d_in[2];
    const float* b1  = (const float*)d_in[3];
    const float* W2  = (const float*)d_in[4];
    const float* b2  = (const float*)d_in[5];
    const float* Wa  = (const float*)d_in[6];
    const float* ba  = (const float*)d_in[7];

    float* out_h = (float*)d_out;
    float* out_a = (float*)d_out + HOUT_ELEMS;

    const int k1_smem = (8192 + 4096 + 128 + 4096 + 2048) * 4;  // 74240 B
    cudaFuncSetAttribute(k1_mlp, cudaFuncAttributeMaxDynamicSharedMemorySize, k1_smem);

    k1_mlp<<<TOTROWS / 32, 256, k1_smem>>>(x, W1, b1, W2, b2, Wa);
    k2_rowsum<<<TOTROWS / 4, 256>>>(adj, ba);
    k3_fused<<<TOTROWS / TI, 256>>>(adj, ba, out_h, out_a);
}

// round 3
// speedup vs baseline: 1.2662x; 1.0100x over previous
#include <cuda_runtime.h>

#define BATCH 2
#define NN    4096
#define CINN  128
#define CC    64
#define TOTROWS (BATCH * NN)       // 8192
#define HOUT_ELEMS (TOTROWS * CC)  // 524288

// ---------------- scratch (device globals; no allocation allowed) ----------
__device__ float g_h[TOTROWS * CC];   // 2 MB
__device__ float g_u[TOTROWS];
__device__ float g_v[TOTROWS];
__device__ float g_invS[TOTROWS];

__device__ __forceinline__ float sigmoidf(float x) {
    return __fdividef(1.0f, 1.0f + __expf(-x));
}

// packed f32x2 helpers -------------------------------------------------------
__device__ __forceinline__ unsigned long long bcast2(float x) {
    unsigned long long r;
    unsigned u = __float_as_uint(x);
    asm("mov.b64 %0, {%1, %2};" : "=l"(r) : "r"(u), "r"(u));
    return r;
}
#define FMA2(d, a, b) asm("fma.rn.f32x2 %0, %1, %2, %0;" : "+l"(d) : "l"(a), "l"(b))
__device__ __forceinline__ float2 unpack2(unsigned long long v) {
    unsigned lo, hi;
    asm("mov.b64 {%0, %1}, %2;" : "=r"(lo), "=r"(hi) : "l"(v));
    float2 f; f.x = __uint_as_float(lo); f.y = __uint_as_float(hi);
    return f;
}

// ===========================================================================
// Kernel 1: h = relu(relu(x@W1+b1)@W2+b2); u = h@Wa[:C]; v = h@Wa[C:]
// ===========================================================================
extern __shared__ float s1[];

__global__ void k1_mlp(const float* __restrict__ x,
                       const float* __restrict__ W1,
                       const float* __restrict__ b1,
                       const float* __restrict__ W2,
                       const float* __restrict__ b2,
                       const float* __restrict__ Wa)
{
    float* sW1 = s1;             // 8192 floats  [i][ch]
    float* sW2 = sW1 + 8192;     // 4096 floats  [i][ch]
    float* sWa = sW2 + 4096;     // 128 floats
    float* sX  = sWa + 128;      // 4096 floats  [r][i]  (reused as sH2 later)
    float* sH1 = sX + 4096;      // 2048 floats  [r][ch]

    const int t = threadIdx.x;
    const int grow0 = blockIdx.x * 32;

    {
        const float4* W1v = (const float4*)W1;
        float4* d = (float4*)sW1;
        #pragma unroll
        for (int p = t; p < 2048; p += 256) d[p] = W1v[p];
        const float4* W2v = (const float4*)W2;
        float4* d2 = (float4*)sW2;
        #pragma unroll
        for (int p = t; p < 1024; p += 256) d2[p] = W2v[p];
        if (t < 32) ((float4*)sWa)[t] = ((const float4*)Wa)[t];
        const float4* Xv = (const float4*)(x + (long)grow0 * CINN);
        float4* dx = (float4*)sX;
        #pragma unroll
        for (int p = t; p < 1024; p += 256) dx[p] = Xv[p];
    }
    __syncthreads();

    const int ch = t & 63;
    const int rg = t >> 6;     // 0..3
    const float bb1 = b1[ch];
    const float bb2 = b2[ch];

    float acc[8];
    #pragma unroll
    for (int k = 0; k < 8; k++) acc[k] = bb1;

    #pragma unroll 4
    for (int i = 0; i < CINN; i += 4) {
        float w0 = sW1[(i + 0) * 64 + ch];
        float w1 = sW1[(i + 1) * 64 + ch];
        float w2 = sW1[(i + 2) * 64 + ch];
        float w3 = sW1[(i + 3) * 64 + ch];
        #pragma unroll
        for (int k = 0; k < 8; k++) {
            const float4 x4 = *(const float4*)(sX + (rg + 4 * k) * CINN + i);
            acc[k] = fmaf(x4.x, w0, acc[k]);
            acc[k] = fmaf(x4.y, w1, acc[k]);
            acc[k] = fmaf(x4.z, w2, acc[k]);
            acc[k] = fmaf(x4.w, w3, acc[k]);
        }
    }
    #pragma unroll
    for (int k = 0; k < 8; k++)
        sH1[(rg + 4 * k) * 64 + ch] = fmaxf(acc[k], 0.0f);
    __syncthreads();

    #pragma unroll
    for (int k = 0; k < 8; k++) acc[k] = bb2;

    #pragma unroll 4
    for (int i = 0; i < CC; i += 4) {
        float w0 = sW2[(i + 0) * 64 + ch];
        float w1 = sW2[(i + 1) * 64 + ch];
        float w2 = sW2[(i + 2) * 64 + ch];
        float w3 = sW2[(i + 3) * 64 + ch];
        #pragma unroll
        for (int k = 0; k < 8; k++) {
            const float4 h4 = *(const float4*)(sH1 + (rg + 4 * k) * 64 + i);
            acc[k] = fmaf(h4.x, w0, acc[k]);
            acc[k] = fmaf(h4.y, w1, acc[k]);
            acc[k] = fmaf(h4.z, w2, acc[k]);
            acc[k] = fmaf(h4.w, w3, acc[k]);
        }
    }

    float* sH2 = sX;
    #pragma unroll
    for (int k = 0; k < 8; k++) {
        const int r = rg + 4 * k;
        const float h2 = fmaxf(acc[k], 0.0f);
        g_h[(long)(grow0 + r) * CC + ch] = h2;
        sH2[r * 64 + ch] = h2;
    }
    __syncthreads();

    const int w = t >> 5, lane = t & 31;
    for (int rr = w * 4; rr < w * 4 + 4; rr++) {
        const float a0 = sH2[rr * 64 + lane];
        const float a1 = sH2[rr * 64 + lane + 32];
        float up = a0 * sWa[lane]      + a1 * sWa[lane + 32];
        float vp = a0 * sWa[64 + lane] + a1 * sWa[96 + lane];
        #pragma unroll
        for (int off = 16; off > 0; off >>= 1) {
            up += __shfl_down_sync(0xffffffffu, up, off);
            vp += __shfl_down_sync(0xffffffffu, vp, off);
        }
        if (lane == 0) { g_u[grow0 + rr] = up; g_v[grow0 + rr] = vp; }
    }
}

// ===========================================================================
// Kernel 2: row sums.
// ===========================================================================
__global__ void k2_rowsum(const float* __restrict__ adj,
                          const float* __restrict__ ba)
{
    __shared__ __align__(16) float sV[NN];
    __shared__ float sRed[8];

    const int t = threadIdx.x;
    const int grow0 = blockIdx.x * 4;
    const int b = grow0 >> 12;

    {
        const float4* vv = (const float4*)(g_v + (long)b * NN);
        float4* d = (float4*)sV;
        #pragma unroll
        for (int p = t; p < 1024; p += 256) d[p] = vv[p];
    }
    __syncthreads();

    const int rg = t >> 6, l64 = t & 63;
    const int grow = grow0 + rg;
    const float u = g_u[grow] + ba[0];
    const float4* ar = (const float4*)(adj + (long)grow * NN);

    float s = 0.0f;
    #pragma unroll 4
    for (int it = 0; it < 16; it++) {
        const int f = l64 + 64 * it;
        const float4 a4 = __ldcs(ar + f);
        const int j = f * 4;
        s += a4.x * sigmoidf(u + sV[j + 0]);
        s += a4.y * sigmoidf(u + sV[j + 1]);
        s += a4.z * sigmoidf(u + sV[j + 2]);
        s += a4.w * sigmoidf(u + sV[j + 3]);
    }
    #pragma unroll
    for (int off = 16; off > 0; off >>= 1)
        s += __shfl_down_sync(0xffffffffu, s, off);
    const int w = t >> 5, lane = t & 31;
    if (lane == 0) sRed[w] = s;
    __syncthreads();
    if (t < 4) {
        const float S = sRed[2 * t] + sRed[2 * t + 1];
        g_invS[grow0 + t] = 1.0f / (S + 1e-10f);
    }
}

// ===========================================================================
// Kernel 3 (fused): TI=64 rows/block, 4x4 microtile, column-major sE for
// vectorized e-loads, register-prefetch pipeline, f32x2 GEMM.
// ===========================================================================
#define TI 64
#define JC 64
#define ESTR 80   // sE stride: [jj][ESTR floats], 16B-aligned LDS.128 reads

__global__ void __launch_bounds__(256, 1)
k3_fused(const float* __restrict__ adj,
         const float* __restrict__ ba,
         float* __restrict__ out_h,
         float* __restrict__ out_a)
{
    __shared__ __align__(16) float sE[JC * ESTR];  // 20KB  [jj][r] col-major
    __shared__ __align__(16) float sH[JC * CC];    // 16KB  [jj][c]
    __shared__ __align__(16) float sV[NN];         // 16KB
    __shared__ float sU[TI];
    __shared__ float sInv[TI];

    const int t = threadIdx.x;
    const int grow0 = blockIdx.x * TI;
    const int b = grow0 >> 12;

    {
        const float4* vv = (const float4*)(g_v + (long)b * NN);
        float4* d = (float4*)sV;
        #pragma unroll
        for (int p = t; p < 1024; p += 256) d[p] = vv[p];
        if (t < TI) { sU[t] = g_u[grow0 + t]; sInv[t] = g_invS[grow0 + t]; }
    }
    const float bav = ba[0];

    // e-pass mapping: thread handles rows (t&15)+16k (k=0..3), float4-col t>>4
    const int erow = t & 15;
    const int ejc  = t >> 4;    // 0..15
    // GEMM mapping: rows 4*tr..4*tr+3, cols 4*tc..4*tc+3
    const int tr = t >> 4;      // 0..15
    const int tc = t & 15;      // 0..15

    unsigned long long acc[2][4];
    #pragma unroll
    for (int p = 0; p < 2; p++)
        #pragma unroll
        for (int q = 0; q < 4; q++) acc[p][q] = 0ULL;

    const float* hbase = g_h + (long)b * NN * CC;

    float4 pa[4];               // prefetched adj (4 row-slices)
    float4 ph[4];               // prefetched h tile (1024 float4 / 256 thr)

    // prologue: prefetch chunk 0
    #pragma unroll
    for (int k = 0; k < 4; k++)
        pa[k] = __ldcs((const float4*)(adj + (long)(grow0 + erow + 16 * k) * NN) + ejc);
    {
        const float4* hv = (const float4*)hbase;
        #pragma unroll
        for (int i = 0; i < 4; i++) ph[i] = hv[t + 256 * i];
    }

    for (int c = 0; c < NN / JC; c++) {
        const int j0 = c * JC;
        __syncthreads();   // previous GEMM done; sV/sU ready on c=0

        // stage h tile
        {
            float4* d = (float4*)sH;
            #pragma unroll
            for (int i = 0; i < 4; i++) d[t + 256 * i] = ph[i];
        }
        // normalized attention tile -> out_a + sE (column-major)
        #pragma unroll
        for (int k = 0; k < 4; k++) {
            const int r = erow + 16 * k;
            const int grow = grow0 + r;
            const float u = sU[r] + bav;
            const float inv = sInv[r];
            const int jj = ejc * 4;
            const float4 a4 = pa[k];
            float4 o;
            o.x = a4.x * sigmoidf(u + sV[j0 + jj + 0]) * inv;
            o.y = a4.y * sigmoidf(u + sV[j0 + jj + 1]) * inv;
            o.z = a4.z * sigmoidf(u + sV[j0 + jj + 2]) * inv;
            o.w = a4.w * sigmoidf(u + sV[j0 + jj + 3]) * inv;
            __stcs((float4*)(out_a + (long)grow * NN + j0) + ejc, o);
            sE[(jj + 0) * ESTR + r] = o.x;
            sE[(jj + 1) * ESTR + r] = o.y;
            sE[(jj + 2) * ESTR + r] = o.z;
            sE[(jj + 3) * ESTR + r] = o.w;
        }
        __syncthreads();

        // prefetch next chunk under the GEMM
        if (c + 1 < NN / JC) {
            const int jn = j0 + JC;
            #pragma unroll
            for (int k = 0; k < 4; k++)
                pa[k] = __ldcs((const float4*)(adj + (long)(grow0 + erow + 16 * k) * NN + jn) + ejc);
            const float4* hv = (const float4*)(hbase + (long)jn * CC);
            #pragma unroll
            for (int i = 0; i < 4; i++) ph[i] = hv[t + 256 * i];
        }

        // GEMM: acc += sE(4 rows)^T * sH(4 cols)
        #pragma unroll 8
        for (int jj = 0; jj < JC; jj++) {
            const ulonglong2 ep = *(const ulonglong2*)(sE + jj * ESTR + 4 * tr);
            const float4 h4 = *(const float4*)(sH + jj * CC + 4 * tc);
            const unsigned long long hb0 = bcast2(h4.x);
            const unsigned long long hb1 = bcast2(h4.y);
            const unsigned long long hb2 = bcast2(h4.z);
            const unsigned long long hb3 = bcast2(h4.w);
            FMA2(acc[0][0], ep.x, hb0);
            FMA2(acc[0][1], ep.x, hb1);
            FMA2(acc[0][2], ep.x, hb2);
            FMA2(acc[0][3], ep.x, hb3);
            FMA2(acc[1][0], ep.y, hb0);
            FMA2(acc[1][1], ep.y, hb1);
            FMA2(acc[1][2], ep.y, hb2);
            FMA2(acc[1][3], ep.y, hb3);
        }
    }

    // epilogue: unpack 4 rows x 4 cols
    #pragma unroll
    for (int p = 0; p < 2; p++) {
        float2 c0 = unpack2(acc[p][0]);
        float2 c1 = unpack2(acc[p][1]);
        float2 c2 = unpack2(acc[p][2]);
        float2 c3 = unpack2(acc[p][3]);
        float4 lo; lo.x = c0.x; lo.y = c1.x; lo.z = c2.x; lo.w = c3.x;
        float4 hi; hi.x = c0.y; hi.y = c1.y; hi.z = c2.y; hi.w = c3.y;
        const int r0 = grow0 + 4 * tr + 2 * p;
        *(float4*)(out_h + (long)r0 * CC + 4 * tc) = lo;
        *(float4*)(out_h + (long)(r0 + 1) * CC + 4 * tc) = hi;
    }
}

// ===========================================================================
extern "C" void kernel_launch(void* const* d_in, const int* in_sizes, int n_in,
                              void* d_out, int out_size)
{
    const float* x   = (const float*)d_in[0];
    const float* adj = (const float*)d_in[1];
    const float* W1  = (const float*)d_in[2];
    const float* b1  = (const float*)d_in[3];
    const float* W2  = (const float*)d_in[4];
    const float* b2  = (const float*)d_in[5];
    const float* Wa  = (const float*)d_in[6];
    const float* ba  = (const float*)d_in[7];

    float* out_h = (float*)d_out;
    float* out_a = (float*)d_out + HOUT_ELEMS;

    const int k1_smem = (8192 + 4096 + 128 + 4096 + 2048) * 4;  // 74240 B
    cudaFuncSetAttribute(k1_mlp, cudaFuncAttributeMaxDynamicSharedMemorySize, k1_smem);

    k1_mlp<<<TOTROWS / 32, 256, k1_smem>>>(x, W1, b1, W2, b2, Wa);
    k2_rowsum<<<TOTROWS / 4, 256>>>(adj, ba);
    k3_fused<<<TOTROWS / TI, 256>>>(adj, ba, out_h, out_a);
}